// round 15
// baseline (speedup 1.0000x reference)
#include <cuda_runtime.h>
#include <cuda_fp16.h>
#include <math.h>
#include <float.h>

#define Bt 32
#define Pp 196
#define Dd 2048
#define Aa 512
#define Ee 512
#define Hh 512
#define Vv 10000
#define Ll 21
#define Tt 20
#define GRD 296

// output layout (float32, concatenated in return-tuple order)
#define OUT_PRED   0
#define OUT_CAPS   6400000
#define OUT_DECLEN 6400672
#define OUT_ALPHA  6400704
#define OUT_SORT   6526144

// g_part regions
#define PART_B 1310720   // lstm partials [8][32][2048]; init reuses [64][32][1024]

typedef unsigned long long ull;

// ---------------- packed f32x2 helpers --------------------------------------
__device__ __forceinline__ ull pk2(float x) {
    ull r; asm("mov.b64 %0, {%1, %1};" : "=l"(r) : "f"(x)); return r;
}
__device__ __forceinline__ void fm2(ull& d, ull a, ull b) {
    asm("fma.rn.f32x2 %0, %1, %2, %0;" : "+l"(d) : "l"(a), "l"(b));
}
__device__ __forceinline__ float2 up2(ull v) {
    float2 r; asm("mov.b64 {%0, %1}, %2;" : "=f"(r.x), "=f"(r.y) : "l"(v)); return r;
}

// ---------------- tf32 mma helpers ------------------------------------------
__device__ __forceinline__ unsigned tf32of(float x) {
    unsigned r; asm("cvt.rna.tf32.f32 %0, %1;" : "=r"(r) : "f"(x)); return r;
}
__device__ __forceinline__ void mma_tf32(float* c, unsigned a0, unsigned a1,
                                         unsigned a2, unsigned a3,
                                         unsigned b0, unsigned b1) {
    asm("mma.sync.aligned.m16n8k8.row.col.f32.tf32.tf32.f32 "
        "{%0,%1,%2,%3}, {%4,%5,%6,%7}, {%8,%9}, {%0,%1,%2,%3};"
        : "+f"(c[0]), "+f"(c[1]), "+f"(c[2]), "+f"(c[3])
        : "r"(a0), "r"(a1), "r"(a2), "r"(a3), "r"(b0), "r"(b1));
}

// ---------------- scratch (device globals; no runtime allocation) ----------
__device__ int   g_sort[Bt];
__device__ int   g_declen[Bt];
__device__ float g_mean[Bt * Dd];
__device__ float g_h[Bt * Hh];
__device__ float g_c[Bt * Hh];
__device__ float g_att1[Bt * Pp * Aa];       // 12.8 MB (fp32)
__device__ __half g_ench[Bt * Pp * Dd];      // 25.6 MB sorted enc, fp16
__device__ float g_x[Bt * 3072];             // [emb | awe | h]
__device__ float g_embs[Bt * Tt * Ee];
__device__ float g_hall[Tt * Bt * Hh];
__device__ float g_part[4460000];            // split-K partials (2 regions)
__device__ __align__(128) unsigned g_arrive;
__device__ __align__(128) unsigned g_release;

__device__ __forceinline__ float sigf(float x) { return 1.0f / (1.0f + expf(-x)); }

// ---------------- two-line grid barrier --------------------------------------
// Arrivals hit g_arrive; pollers spin on g_release (written once per phase by
// the last arriver) -> atomic line is never contended by polls.
__device__ __forceinline__ void gsync2(unsigned ph) {
    __syncthreads();
    if (threadIdx.x == 0) {
        __threadfence();
        unsigned old = atomicAdd(&g_arrive, 1u);
        if (old == ph * GRD - 1u) {
            atomicExch(&g_release, ph);
        } else {
            while (*((volatile unsigned*)&g_release) < ph) { }
        }
        __threadfence();
    }
    __syncthreads();
}

// ---------------- prep: argsort + emb gather + mean + enc fp16 copy ---------
__global__ void __launch_bounds__(256) prep_kernel(
    const int* __restrict__ caplen, const int* __restrict__ caps_in,
    const float* __restrict__ emb,  const float* __restrict__ enc,
    float* __restrict__ out)
{
    __shared__ int len[Bt];
    __shared__ int sloc[Bt];
    int tid = threadIdx.x, bid = blockIdx.x;
    if (tid < Bt) len[tid] = caplen[tid];
    __syncthreads();
    if (tid < Bt) {
        int myl = len[tid], rank = 0;
        for (int j = 0; j < Bt; j++) {
            int lj = len[j];
            if (lj > myl || (lj == myl && j < tid)) rank++;
        }
        sloc[rank] = tid;
    }
    __syncthreads();
    if (bid == 0) {
        if (tid < Bt) {
            int sb = sloc[tid], dl = len[sb] - 1;
            g_sort[tid] = sb; g_declen[tid] = dl;
            out[OUT_SORT + tid]   = (float)sb;
            out[OUT_DECLEN + tid] = (float)dl;
            for (int l = 0; l < Ll; l++)
                out[OUT_CAPS + tid * Ll + l] = (float)caps_in[sb * Ll + l];
        }
        if (tid == 0) { g_arrive = 0u; g_release = 0u; }
    }
    for (int i = bid * 256 + tid; i < Bt * Tt * Ee; i += 256 * 256) {
        int b = i / (Tt * Ee);
        int r = i - b * (Tt * Ee);
        int t = r >> 9, j = r & 511;
        int tok = caps_in[sloc[b] * Ll + t];
        float v = emb[(size_t)tok * Ee + j];
        g_embs[i] = v;
        if (t == 0) g_x[b * 3072 + j] = v;
    }
    for (int i4 = bid * 256 + tid; i4 < Bt * Pp * Dd / 4; i4 += 256 * 256) {
        int i = i4 * 4;
        int b = i / (Pp * Dd);
        int r = i - b * (Pp * Dd);
        float4 v = *(const float4*)(enc + (size_t)sloc[b] * Pp * Dd + r);
        __half2 lo = __floats2half2_rn(v.x, v.y);
        __half2 hi = __floats2half2_rn(v.z, v.w);
        *(__half2*)(g_ench + i)     = lo;
        *(__half2*)(g_ench + i + 2) = hi;
    }
    {
        int b = bid >> 3, dc = bid & 7, d = dc * 256 + tid;
        const float* base = enc + (size_t)sloc[b] * Pp * Dd + d;
        float s0 = 0.f, s1 = 0.f, s2 = 0.f, s3 = 0.f;
        for (int p = 0; p < Pp; p += 4) {
            s0 += base[(size_t)p * Dd];
            s1 += base[(size_t)(p + 1) * Dd];
            s2 += base[(size_t)(p + 2) * Dd];
            s3 += base[(size_t)(p + 3) * Dd];
        }
        g_mean[b * Dd + d] = (s0 + s1 + s2 + s3) / 196.0f;
    }
}

// ---------------- skinny split-K body (f32x2, 32 rows) — init only ----------
__device__ __forceinline__ void skinny_body(const float* xs, const float* W,
                                            int st, int kPer,
                                            float* prow, int N) {
    ull acc[16];
#pragma unroll
    for (int i = 0; i < 16; i++) acc[i] = 0ULL;
    float w0 = W[0];
    float w1 = W[(size_t)st];
    float w2 = W[(size_t)2 * st];
    float w3 = W[(size_t)3 * st];
#pragma unroll 1
    for (int kk = 0; kk < kPer; kk += 4) {
        int kn = (kk + 4 < kPer) ? (kk + 4) : kk;
        float nw0 = W[(size_t)(kn + 0) * st];
        float nw1 = W[(size_t)(kn + 1) * st];
        float nw2 = W[(size_t)(kn + 2) * st];
        float nw3 = W[(size_t)(kn + 3) * st];
        const ulonglong2* x0 = (const ulonglong2*)(xs + (kk + 0) * 36);
        const ulonglong2* x1 = (const ulonglong2*)(xs + (kk + 1) * 36);
        const ulonglong2* x2 = (const ulonglong2*)(xs + (kk + 2) * 36);
        const ulonglong2* x3 = (const ulonglong2*)(xs + (kk + 3) * 36);
        ull wp;
        wp = pk2(w0);
#pragma unroll
        for (int i = 0; i < 8; i++) { ulonglong2 v = x0[i]; fm2(acc[2*i], v.x, wp); fm2(acc[2*i+1], v.y, wp); }
        wp = pk2(w1);
#pragma unroll
        for (int i = 0; i < 8; i++) { ulonglong2 v = x1[i]; fm2(acc[2*i], v.x, wp); fm2(acc[2*i+1], v.y, wp); }
        wp = pk2(w2);
#pragma unroll
        for (int i = 0; i < 8; i++) { ulonglong2 v = x2[i]; fm2(acc[2*i], v.x, wp); fm2(acc[2*i+1], v.y, wp); }
        wp = pk2(w3);
#pragma unroll
        for (int i = 0; i < 8; i++) { ulonglong2 v = x3[i]; fm2(acc[2*i], v.x, wp); fm2(acc[2*i+1], v.y, wp); }
        w0 = nw0; w1 = nw1; w2 = nw2; w3 = nw3;
    }
#pragma unroll
    for (int mp = 0; mp < 16; mp++) {
        float2 v = up2(acc[mp]);
        prow[(size_t)(2 * mp) * N]     = v.x;
        prow[(size_t)(2 * mp + 1) * N] = v.y;
    }
}

// ---------------- 32x64 tf32 MMA tile, double-buffered ----------------------
__device__ void mma32_tile(const float* xbase, int xstride, int kOff, int kLen,
                           const float* W0, const float* W1, int kSplit, int wst,
                           const float* WA, const float* WC, int mode,
                           int bn, float* pout, int N,
                           unsigned* As, unsigned* Bs) {
    int tid = threadIdx.x;
    int warp = tid >> 5, lane = tid & 31;
    int row = lane >> 2, tig = lane & 3;
    int wn = warp * 8;
    int arow = tid >> 3;
    int ak = (tid & 7) * 2;
    int bkk = tid >> 4;
    int bn4 = (tid & 15) * 4;

    float acc[2][4];
#pragma unroll
    for (int i = 0; i < 2; i++)
#pragma unroll
        for (int q = 0; q < 4; q++) acc[i][q] = 0.f;

    int nIter = kLen >> 4;
    auto stage = [&](int it, int buf) {
        const float* xp = xbase + (size_t)arow * xstride + kOff + it * 16 + ak;
        float2 xv = *(const float2*)xp;
        unsigned* A = As + buf * 544;
        A[arow * 17 + ak]     = tf32of(xv.x);
        A[arow * 17 + ak + 1] = tf32of(xv.y);
        int kg = kOff + it * 16 + bkk;
        const float* wp;
        if (mode == 0) {
            wp = (kg < kSplit) ? W0 + (size_t)kg * wst + bn + bn4
                               : W1 + (size_t)(kg - kSplit) * wst + bn + bn4;
        } else {
            int gn = bn + bn4;
            wp = (gn < 512) ? WA + (size_t)kg * 512 + gn
                            : WC + (size_t)kg * 2048 + (gn - 512);
        }
        float4 wv = *(const float4*)wp;
        unsigned* B = Bs + buf * 1088;
        B[(bn4 + 0) * 17 + bkk] = tf32of(wv.x);
        B[(bn4 + 1) * 17 + bkk] = tf32of(wv.y);
        B[(bn4 + 2) * 17 + bkk] = tf32of(wv.z);
        B[(bn4 + 3) * 17 + bkk] = tf32of(wv.w);
    };

    stage(0, 0);
    __syncthreads();
#pragma unroll 1
    for (int it = 0; it < nIter; it++) {
        int cur = it & 1;
        if (it + 1 < nIter) stage(it + 1, cur ^ 1);
        unsigned* A = As + cur * 544;
        unsigned* B = Bs + cur * 1088;
#pragma unroll
        for (int ks = 0; ks < 2; ks++) {
            int kb = ks * 8;
            unsigned b0 = B[(wn + row) * 17 + kb + tig];
            unsigned b1 = B[(wn + row) * 17 + kb + tig + 4];
#pragma unroll
            for (int mt = 0; mt < 2; mt++) {
                int m = mt * 16;
                unsigned a0 = A[(m + row) * 17 + kb + tig];
                unsigned a1 = A[(m + row + 8) * 17 + kb + tig];
                unsigned a2 = A[(m + row) * 17 + kb + tig + 4];
                unsigned a3 = A[(m + row + 8) * 17 + kb + tig + 4];
                mma_tf32(acc[mt], a0, a1, a2, a3, b0, b1);
            }
        }
        __syncthreads();
    }
#pragma unroll
    for (int mt = 0; mt < 2; mt++) {
        int m = mt * 16 + row;
        int n = bn + wn + 2 * tig;
        pout[(size_t)m * N + n]           = acc[mt][0];
        pout[(size_t)m * N + n + 1]       = acc[mt][1];
        pout[(size_t)(m + 8) * N + n]     = acc[mt][2];
        pout[(size_t)(m + 8) * N + n + 1] = acc[mt][3];
    }
}

// ---------------- tf32 tiles (att1/fc, unchanged) ----------------------------
__device__ void att1_tile(int bx, int by,
                          const float* __restrict__ enc,
                          const float* __restrict__ W,
                          const float* __restrict__ bias,
                          unsigned* As, unsigned* Bs) {
    int tid = threadIdx.x;
    int warp = tid >> 5, lane = tid & 31;
    int bm = bx * 128, bn = by * 64;
    int wm = (warp & 3) * 32, wn = (warp >> 2) * 32;
    int row = lane >> 2, tig = lane & 3;
    int m0 = tid >> 2;
    int kq4 = (tid & 3) * 4;
    const float *arow0, *arow1;
    {
        int gm = bm + m0; int b = gm / 196, p = gm - b * 196;
        arow0 = enc + ((size_t)g_sort[b] * Pp + p) * Dd + kq4;
        gm = bm + m0 + 64; b = gm / 196; p = gm - b * 196;
        arow1 = enc + ((size_t)g_sort[b] * Pp + p) * Dd + kq4;
    }
    float acc[2][4][4];
#pragma unroll
    for (int i = 0; i < 2; i++)
#pragma unroll
        for (int j = 0; j < 4; j++)
#pragma unroll
            for (int q = 0; q < 4; q++) acc[i][j][q] = 0.f;

    for (int k0 = 0; k0 < Dd; k0 += 16) {
        float4 va = *(const float4*)(arow0 + k0);
        As[m0 * 37 + kq4 + 0] = tf32of(va.x);
        As[m0 * 37 + kq4 + 1] = tf32of(va.y);
        As[m0 * 37 + kq4 + 2] = tf32of(va.z);
        As[m0 * 37 + kq4 + 3] = tf32of(va.w);
        va = *(const float4*)(arow1 + k0);
        As[(m0 + 64) * 37 + kq4 + 0] = tf32of(va.x);
        As[(m0 + 64) * 37 + kq4 + 1] = tf32of(va.y);
        As[(m0 + 64) * 37 + kq4 + 2] = tf32of(va.z);
        As[(m0 + 64) * 37 + kq4 + 3] = tf32of(va.w);
#pragma unroll
        for (int i = 0; i < 4; i++) {
            int idx = tid + i * 256;
            int kk = idx >> 6, n = idx & 63;
            Bs[n * 21 + kk] = tf32of(W[(size_t)(k0 + kk) * Aa + bn + n]);
        }
        __syncthreads();
#pragma unroll
        for (int ks = 0; ks < 2; ks++) {
            int kb = ks * 8;
            unsigned b0[4], b1[4];
#pragma unroll
            for (int nt = 0; nt < 4; nt++) {
                int n = wn + nt * 8 + row;
                b0[nt] = Bs[n * 21 + kb + tig];
                b1[nt] = Bs[n * 21 + kb + tig + 4];
            }
#pragma unroll
            for (int mt = 0; mt < 2; mt++) {
                int m = wm + mt * 16;
                unsigned a0 = As[(m + row) * 37 + kb + tig];
                unsigned a1 = As[(m + row + 8) * 37 + kb + tig];
                unsigned a2 = As[(m + row) * 37 + kb + tig + 4];
                unsigned a3 = As[(m + row + 8) * 37 + kb + tig + 4];
#pragma unroll
                for (int nt = 0; nt < 4; nt++)
                    mma_tf32(acc[mt][nt], a0, a1, a2, a3, b0[nt], b1[nt]);
            }
        }
        __syncthreads();
    }
#pragma unroll
    for (int mt = 0; mt < 2; mt++) {
        int mrow = bm + wm + mt * 16 + row;
#pragma unroll
        for (int nt = 0; nt < 4; nt++) {
            int col = bn + wn + nt * 8 + 2 * tig;
            float b0v = bias[col], b1v = bias[col + 1];
            g_att1[(size_t)mrow * Aa + col]           = acc[mt][nt][0] + b0v;
            g_att1[(size_t)mrow * Aa + col + 1]       = acc[mt][nt][1] + b1v;
            g_att1[(size_t)(mrow + 8) * Aa + col]     = acc[mt][nt][2] + b0v;
            g_att1[(size_t)(mrow + 8) * Aa + col + 1] = acc[mt][nt][3] + b1v;
        }
    }
}

__device__ void fc_tile(int bx, int by,
                        const float* __restrict__ fc_w,
                        const float* __restrict__ fc_b,
                        float* __restrict__ out,
                        unsigned* As, unsigned* Bs) {
    int tid = threadIdx.x;
    int warp = tid >> 5, lane = tid & 31;
    int bm = bx * 128, bn = by * 64;
    int wm = (warp & 3) * 32, wn = (warp >> 2) * 32;
    int row = lane >> 2, tig = lane & 3;
    int m0 = tid >> 2;
    int kq4 = (tid & 3) * 4;
    const float* arow0 = g_hall + (size_t)(bm + m0) * Hh + kq4;
    const float* arow1 = g_hall + (size_t)(bm + m0 + 64) * Hh + kq4;

    float acc[2][4][4];
#pragma unroll
    for (int i = 0; i < 2; i++)
#pragma unroll
        for (int j = 0; j < 4; j++)
#pragma unroll
            for (int q = 0; q < 4; q++) acc[i][j][q] = 0.f;

    for (int k0 = 0; k0 < Hh; k0 += 16) {
        float4 va = *(const float4*)(arow0 + k0);
        As[m0 * 37 + kq4 + 0] = tf32of(va.x);
        As[m0 * 37 + kq4 + 1] = tf32of(va.y);
        As[m0 * 37 + kq4 + 2] = tf32of(va.z);
        As[m0 * 37 + kq4 + 3] = tf32of(va.w);
        va = *(const float4*)(arow1 + k0);
        As[(m0 + 64) * 37 + kq4 + 0] = tf32of(va.x);
        As[(m0 + 64) * 37 + kq4 + 1] = tf32of(va.y);
        As[(m0 + 64) * 37 + kq4 + 2] = tf32of(va.z);
        As[(m0 + 64) * 37 + kq4 + 3] = tf32of(va.w);
#pragma unroll
        for (int i = 0; i < 4; i++) {
            int idx = tid + i * 256;
            int kk = idx >> 6, n = idx & 63;
            int gn = bn + n;
            Bs[n * 21 + kk] = (gn < Vv) ? tf32of(fc_w[(size_t)(k0 + kk) * Vv + gn]) : 0u;
        }
        __syncthreads();
#pragma unroll
        for (int ks = 0; ks < 2; ks++) {
            int kb = ks * 8;
            unsigned b0[4], b1[4];
#pragma unroll
            for (int nt = 0; nt < 4; nt++) {
                int n = wn + nt * 8 + row;
                b0[nt] = Bs[n * 21 + kb + tig];
                b1[nt] = Bs[n * 21 + kb + tig + 4];
            }
#pragma unroll
            for (int mt = 0; mt < 2; mt++) {
                int m = wm + mt * 16;
                unsigned a0 = As[(m + row) * 37 + kb + tig];
                unsigned a1 = As[(m + row + 8) * 37 + kb + tig];
                unsigned a2 = As[(m + row) * 37 + kb + tig + 4];
                unsigned a3 = As[(m + row + 8) * 37 + kb + tig + 4];
#pragma unroll
                for (int nt = 0; nt < 4; nt++)
                    mma_tf32(acc[mt][nt], a0, a1, a2, a3, b0[nt], b1[nt]);
            }
        }
        __syncthreads();
    }
#pragma unroll
    for (int mt = 0; mt < 2; mt++) {
#pragma unroll
        for (int rr = 0; rr < 2; rr++) {
            int m = bm + wm + mt * 16 + row + rr * 8;
            int t = m >> 5, b = m & 31;
            int active = (t < g_declen[b]);
            size_t obase = OUT_PRED + ((size_t)b * Tt + t) * Vv;
#pragma unroll
            for (int nt = 0; nt < 4; nt++) {
                int col = bn + wn + nt * 8 + 2 * tig;
                if (col >= Vv) continue;
                float v0 = acc[mt][nt][2 * rr + 0];
                float v1 = acc[mt][nt][2 * rr + 1];
                out[obase + col] = active ? (v0 + fc_b[col]) : 0.f;
                if (col + 1 < Vv)
                    out[obase + col + 1] = active ? (v1 + fc_b[col + 1]) : 0.f;
            }
        }
    }
}

// ---------------- mega kernel ------------------------------------------------
__global__ void __launch_bounds__(256, 2) mega_kernel(
    const float* __restrict__ enc,
    const float* __restrict__ enc_att_w, const float* __restrict__ enc_att_b,
    const float* __restrict__ init_h_w,  const float* __restrict__ init_h_b,
    const float* __restrict__ init_c_w,  const float* __restrict__ init_c_b,
    const float* __restrict__ dec_att_w, const float* __restrict__ dec_att_b,
    const float* __restrict__ f_beta_w,  const float* __restrict__ f_beta_b,
    const float* __restrict__ full_w,    const float* __restrict__ full_b,
    const float* __restrict__ lstm_w_ih, const float* __restrict__ lstm_w_hh,
    const float* __restrict__ lstm_b,
    const float* __restrict__ fc_w,      const float* __restrict__ fc_b,
    float* __restrict__ out)
{
    __shared__ __align__(16) unsigned char SM[24832];
    __shared__ float red[16];
    unsigned* As = (unsigned*)SM;
    unsigned* Bs = (unsigned*)(SM + 18944);
    unsigned* As2 = (unsigned*)SM;                 // 2*544*4  = 4352B
    unsigned* Bs2 = (unsigned*)(SM + 4352);        // 2*1088*4 = 8704B
    float* xs  = (float*)SM;
    float* sbf = (float*)SM;

    const int bid = blockIdx.x, tid = threadIdx.x;
    const int warp = tid >> 5, lane = tid & 31;
    unsigned ph = 0;

    // ---- Phase A0: att1 tiles + init split-K parts -------------------------
    for (int vb = bid; vb < 392; vb += GRD)
        att1_tile(vb % 49, vb / 49, enc, enc_att_w, enc_att_b, As, Bs);
    for (int u = bid; u < 256; u += GRD) {
        int ky = u >> 2, nx = u & 3;
        int kBeg = ky * 32;
        __syncthreads();
        for (int i = tid; i < 32 * 32; i += 256) {
            int m = i >> 5, kk = i & 31;
            xs[kk * 36 + m] = g_mean[m * 2048 + kBeg + kk];
        }
        __syncthreads();
        int n = nx * 256 + tid;
        const float* W = (n < 512) ? (init_h_w + (size_t)kBeg * 512 + n)
                                   : (init_c_w + (size_t)kBeg * 512 + (n - 512));
        skinny_body(xs, W, 512, 32,
                    g_part + PART_B + (size_t)(ky * 32) * 1024 + n, 1024);
    }
    gsync2(++ph);

    // ---- init reduce -> h0/c0 ----------------------------------------------
    if (bid < 128) {
        int idx = bid * 256 + tid;
        int m = idx >> 10, n = idx & 1023;
        float s0 = 0.f, s1 = 0.f;
#pragma unroll 8
        for (int ks = 0; ks < 64; ks += 2) {
            s0 += g_part[PART_B + ((size_t)(ks * 32 + m)) * 1024 + n];
            s1 += g_part[PART_B + ((size_t)((ks + 1) * 32 + m)) * 1024 + n];
        }
        float s = s0 + s1;
        if (n < 512) {
            float v = s + init_h_b[n];
            g_h[m * 512 + n] = v;
            g_x[m * 3072 + 2560 + n] = v;
        } else {
            g_c[m * 512 + (n - 512)] = s + init_c_b[n - 512];
        }
    }
    gsync2(++ph);

    // ---- decode loop: 4 full barriers/step ---------------------------------
    for (int t = 0; t < Tt; t++) {
        // PA: hproj (80 blk, KS2) + lstm emb/h k-chunks (128 blk, kLen 256)
        if (bid < 208) {
            if (bid < 80) {
                int nx = bid % 40, ky = bid / 40;      // ky 0..1
                mma32_tile(g_h, 512, ky * 256, 256,
                           0, 0, 0, 0, dec_att_w, f_beta_w, 1,
                           nx * 64,
                           g_part + (size_t)(ky * 32) * 2560, 2560,
                           As2, Bs2);
            } else {
                int u2 = bid - 80;
                int nx = u2 & 31, s = u2 >> 5;         // s 0..3
                int xk = (s < 2) ? s * 256 : 2560 + (s - 2) * 256;
                mma32_tile(g_x, 3072, xk, 256,
                           lstm_w_ih, lstm_w_hh, 2560, 2048, 0, 0, 0,
                           nx * 64,
                           g_part + PART_B + (size_t)(s * 32) * 2048, 2048,
                           As2, Bs2);
            }
        }
        gsync2(++ph);

        // PBC: (2 blocks per b) att2 reduce + scores(all,smem) + softmax
        //      + gate + awe(d-half) -> x. No cross-block sync inside.
        if (bid < 64) {
            int b = bid >> 1, half = bid & 1;
#pragma unroll
            for (int rep = 0; rep < 2; rep++) {
                int aa = rep * 256 + tid;
                float s0 = dec_att_b[aa];
#pragma unroll
                for (int ks = 0; ks < 2; ks++)
                    s0 += g_part[(size_t)(ks * 32 + b) * 2560 + aa];
                sbf[aa] = s0;
                sbf[512 + aa] = full_w[aa];
            }
            __syncthreads();
            float fb = *full_b;
            for (int p = warp; p < 196; p += 8) {
                const float4* rowp = (const float4*)(g_att1 + (size_t)(b * 196 + p) * 512);
                float s = 0.f;
#pragma unroll
                for (int a4 = lane; a4 < 128; a4 += 32) {
                    float4 v = rowp[a4];
                    float4 tt = *(const float4*)&sbf[a4 * 4];
                    float4 w = *(const float4*)&sbf[512 + a4 * 4];
                    s += fmaxf(v.x + tt.x, 0.f) * w.x;
                    s += fmaxf(v.y + tt.y, 0.f) * w.y;
                    s += fmaxf(v.z + tt.z, 0.f) * w.z;
                    s += fmaxf(v.w + tt.w, 0.f) * w.w;
                }
#pragma unroll
                for (int o = 16; o; o >>= 1) s += __shfl_down_sync(0xffffffffu, s, o);
                if (lane == 0) sbf[1024 + p] = s + fb;
            }
            __syncthreads();
            // softmax over sbf[1024..1220)
            float e = (tid < 196) ? sbf[1024 + tid] : -FLT_MAX;
            float m = e;
#pragma unroll
            for (int o = 16; o; o >>= 1)
                m = fmaxf(m, __shfl_xor_sync(0xffffffffu, m, o));
            if (lane == 0) red[warp] = m;
            __syncthreads();
            if (tid == 0) {
                float mm = red[0];
#pragma unroll
                for (int q = 1; q < 8; q++) mm = fmaxf(mm, red[q]);
                red[8] = mm;
            }
            __syncthreads();
            float mx = red[8];
            float ex = (tid < 196) ? expf(e - mx) : 0.f;
            float ss = ex;
#pragma unroll
            for (int o = 16; o; o >>= 1) ss += __shfl_xor_sync(0xffffffffu, ss, o);
            if (lane == 0) red[warp] = ss;
            __syncthreads();
            if (tid == 0) {
                float s2 = 0.f;
#pragma unroll
                for (int q = 0; q < 8; q++) s2 += red[q];
                red[9] = s2;
            }
            __syncthreads();
            float inv = 1.f / red[9];
            if (tid < 196) sbf[1024 + tid] = ex * inv;
            __syncthreads();
            int active = (t < g_declen[b]);
            if (half == 0 && tid < 196)
                out[OUT_ALPHA + (size_t)(b * Tt + t) * 196 + tid] =
                    active ? sbf[1024 + tid] : 0.f;
            // awe for this d-half (4 cols per thread), alpha from smem
            const __half* basep = g_ench + (size_t)b * Pp * Dd + half * 1024 + tid;
            float acc4[4] = {0.f, 0.f, 0.f, 0.f};
#pragma unroll 1
            for (int p = 0; p < 196; p += 2) {
                float al0 = sbf[1024 + p], al1 = sbf[1024 + p + 1];
#pragma unroll
                for (int i = 0; i < 4; i++) {
                    acc4[i] += __half2float(basep[(size_t)p * Dd + i * 256]) * al0;
                    acc4[i] += __half2float(basep[(size_t)(p + 1) * Dd + i * 256]) * al1;
                }
            }
#pragma unroll
            for (int i = 0; i < 4; i++) {
                int d = half * 1024 + i * 256 + tid;
                float gp = f_beta_b[d];
#pragma unroll
                for (int ks = 0; ks < 2; ks++)
                    gp += g_part[(size_t)(ks * 32 + b) * 2560 + 512 + d];
                g_x[b * 3072 + 512 + d] = acc4[i] * sigf(gp);
            }
        }
        gsync2(++ph);

        // PD: lstm awe k-chunks (128 blk, 32 n-tiles x KS4, kLen 512)
        if (bid < 128) {
            int nx = bid & 31, ky = bid >> 5;          // ky 0..3
            mma32_tile(g_x, 3072, 512 + ky * 512, 512,
                       lstm_w_ih, lstm_w_hh, 2560, 2048, 0, 0, 0,
                       nx * 64,
                       g_part + PART_B + (size_t)((4 + ky) * 32) * 2048, 2048,
                       As2, Bs2);
        }
        gsync2(++ph);

        // PE: LSTM cell (64 blk), KS=8 (rows 0-3 from PA, 4-7 from PD)
        if (bid < 64) {
            int idx = bid * 256 + tid;
            int b = idx >> 9, j = idx & 511;
            float s[4];
#pragma unroll
            for (int g = 0; g < 4; g++) s[g] = lstm_b[g * 512 + j];
#pragma unroll
            for (int ks = 0; ks < 8; ks++) {
                size_t base0 = PART_B + (size_t)(ks * 32 + b) * 2048 + j;
#pragma unroll
                for (int g = 0; g < 4; g++)
                    s[g] += g_part[base0 + g * 512];
            }
            float c_old = g_c[idx];
            float c_new = sigf(s[1]) * c_old + sigf(s[0]) * tanhf(s[2]);
            float h_new = sigf(s[3]) * tanhf(c_new);
            g_hall[((size_t)t * Bt + b) * Hh + j] = h_new;
            int active = (t < g_declen[b]);
            float h_keep = active ? h_new : g_h[idx];
            float c_keep = active ? c_new : c_old;
            g_h[idx] = h_keep;
            g_c[idx] = c_keep;
            g_x[b * 3072 + 2560 + j] = h_keep;
            if (t + 1 < Tt)
                g_x[b * 3072 + j] = g_embs[((size_t)b * Tt + (t + 1)) * Ee + j];
        }
        gsync2(++ph);
    }

    // ---- FC: preds = h_all @ fc_w + b (785 tiles) ---------------------------
    for (int vb = bid; vb < 785; vb += GRD)
        fc_tile(vb % 5, vb / 5, fc_w, fc_b, out, As, Bs);
}

// ---------------- launch ----------------------------------------------------
extern "C" void kernel_launch(void* const* d_in, const int* in_sizes, int n_in,
                              void* d_out, int out_size) {
    const float* enc        = (const float*)d_in[0];
    const int*   caps_in    = (const int*)d_in[1];
    const int*   caplen     = (const int*)d_in[2];
    const float* enc_att_w  = (const float*)d_in[3];
    const float* enc_att_b  = (const float*)d_in[4];
    const float* dec_att_w  = (const float*)d_in[5];
    const float* dec_att_b  = (const float*)d_in[6];
    const float* full_att_w = (const float*)d_in[7];
    const float* full_att_b = (const float*)d_in[8];
    const float* emb        = (const float*)d_in[9];
    const float* init_h_w   = (const float*)d_in[10];
    const float* init_h_b   = (const float*)d_in[11];
    const float* init_c_w   = (const float*)d_in[12];
    const float* init_c_b   = (const float*)d_in[13];
    const float* f_beta_w   = (const float*)d_in[14];
    const float* f_beta_b   = (const float*)d_in[15];
    const float* lstm_w_ih  = (const float*)d_in[16];
    const float* lstm_w_hh  = (const float*)d_in[17];
    const float* lstm_b     = (const float*)d_in[18];
    const float* fc_w       = (const float*)d_in[19];
    const float* fc_b       = (const float*)d_in[20];
    float* out = (float*)d_out;

    prep_kernel<<<256, 256>>>(caplen, caps_in, emb, enc, out);
    mega_kernel<<<GRD, 256>>>(enc,
                              enc_att_w, enc_att_b,
                              init_h_w, init_h_b,
                              init_c_w, init_c_b,
                              dec_att_w, dec_att_b,
                              f_beta_w, f_beta_b,
                              full_att_w, full_att_b,
                              lstm_w_ih, lstm_w_hh, lstm_b,
                              fc_w, fc_b,
                              out);
}

// round 16
// speedup vs baseline: 1.5377x; 1.5377x over previous
#include <cuda_runtime.h>
#include <cuda_fp16.h>
#include <math.h>
#include <float.h>

#define Bt 32
#define Pp 196
#define Dd 2048
#define Aa 512
#define Ee 512
#define Hh 512
#define Vv 10000
#define Ll 21
#define Tt 20
#define GRD 296

// output layout (float32, concatenated in return-tuple order)
#define OUT_PRED   0
#define OUT_CAPS   6400000
#define OUT_DECLEN 6400672
#define OUT_ALPHA  6400704
#define OUT_SORT   6526144

// g_part regions
#define PART_B 1310720   // lstm partials [8][32][2048]; init reuses [64][32][1024]

typedef unsigned long long ull;

// ---------------- packed f32x2 helpers --------------------------------------
__device__ __forceinline__ ull pk2(float x) {
    ull r; asm("mov.b64 %0, {%1, %1};" : "=l"(r) : "f"(x)); return r;
}
__device__ __forceinline__ void fm2(ull& d, ull a, ull b) {
    asm("fma.rn.f32x2 %0, %1, %2, %0;" : "+l"(d) : "l"(a), "l"(b));
}
__device__ __forceinline__ float2 up2(ull v) {
    float2 r; asm("mov.b64 {%0, %1}, %2;" : "=f"(r.x), "=f"(r.y) : "l"(v)); return r;
}

// ---------------- tf32 mma helpers ------------------------------------------
__device__ __forceinline__ unsigned tf32of(float x) {
    unsigned r; asm("cvt.rna.tf32.f32 %0, %1;" : "=r"(r) : "f"(x)); return r;
}
__device__ __forceinline__ void mma_tf32(float* c, unsigned a0, unsigned a1,
                                         unsigned a2, unsigned a3,
                                         unsigned b0, unsigned b1) {
    asm("mma.sync.aligned.m16n8k8.row.col.f32.tf32.tf32.f32 "
        "{%0,%1,%2,%3}, {%4,%5,%6,%7}, {%8,%9}, {%0,%1,%2,%3};"
        : "+f"(c[0]), "+f"(c[1]), "+f"(c[2]), "+f"(c[3])
        : "r"(a0), "r"(a1), "r"(a2), "r"(a3), "r"(b0), "r"(b1));
}

// ---------------- scratch (device globals; no runtime allocation) ----------
__device__ int   g_sort[Bt];
__device__ int   g_declen[Bt];
__device__ float g_mean[Bt * Dd];
__device__ float g_h[Bt * Hh];
__device__ float g_c[Bt * Hh];
__device__ float g_att1[Bt * Pp * Aa];       // 12.8 MB (fp32)
__device__ __half g_ench[Bt * Pp * Dd];      // 25.6 MB sorted enc, fp16
__device__ float g_escore[Bt * Pp];
__device__ float g_x[Bt * 3072];             // [emb | awe | h]
__device__ float g_embs[Bt * Tt * Ee];
__device__ float g_hall[Tt * Bt * Hh];
__device__ float g_part[4460000];            // split-K partials (2 regions)
__device__ __align__(128) unsigned g_arrive;
__device__ __align__(128) unsigned g_release;

__device__ __forceinline__ float sigf(float x) { return 1.0f / (1.0f + expf(-x)); }

// ---------------- two-line grid barrier --------------------------------------
// Arrivals hit g_arrive; pollers spin on g_release (written once per phase by
// the last arriver) -> the atomic line is never contended by poll reads.
__device__ __forceinline__ void gsync(unsigned ph) {
    __syncthreads();
    if (threadIdx.x == 0) {
        __threadfence();
        unsigned old = atomicAdd(&g_arrive, 1u);
        if (old == ph * GRD - 1u) {
            atomicExch(&g_release, ph);
        } else {
            while (*((volatile unsigned*)&g_release) < ph) { }
        }
        __threadfence();
    }
    __syncthreads();
}

// ---------------- prep: argsort + emb gather + mean + enc fp16 copy ---------
__global__ void __launch_bounds__(256) prep_kernel(
    const int* __restrict__ caplen, const int* __restrict__ caps_in,
    const float* __restrict__ emb,  const float* __restrict__ enc,
    float* __restrict__ out)
{
    __shared__ int len[Bt];
    __shared__ int sloc[Bt];
    int tid = threadIdx.x, bid = blockIdx.x;
    if (tid < Bt) len[tid] = caplen[tid];
    __syncthreads();
    if (tid < Bt) {
        int myl = len[tid], rank = 0;
        for (int j = 0; j < Bt; j++) {
            int lj = len[j];
            if (lj > myl || (lj == myl && j < tid)) rank++;
        }
        sloc[rank] = tid;
    }
    __syncthreads();
    if (bid == 0) {
        if (tid < Bt) {
            int sb = sloc[tid], dl = len[sb] - 1;
            g_sort[tid] = sb; g_declen[tid] = dl;
            out[OUT_SORT + tid]   = (float)sb;
            out[OUT_DECLEN + tid] = (float)dl;
            for (int l = 0; l < Ll; l++)
                out[OUT_CAPS + tid * Ll + l] = (float)caps_in[sb * Ll + l];
        }
        if (tid == 0) { g_arrive = 0u; g_release = 0u; }
    }
    for (int i = bid * 256 + tid; i < Bt * Tt * Ee; i += 256 * 256) {
        int b = i / (Tt * Ee);
        int r = i - b * (Tt * Ee);
        int t = r >> 9, j = r & 511;
        int tok = caps_in[sloc[b] * Ll + t];
        float v = emb[(size_t)tok * Ee + j];
        g_embs[i] = v;
        if (t == 0) g_x[b * 3072 + j] = v;
    }
    for (int i4 = bid * 256 + tid; i4 < Bt * Pp * Dd / 4; i4 += 256 * 256) {
        int i = i4 * 4;
        int b = i / (Pp * Dd);
        int r = i - b * (Pp * Dd);
        float4 v = *(const float4*)(enc + (size_t)sloc[b] * Pp * Dd + r);
        __half2 lo = __floats2half2_rn(v.x, v.y);
        __half2 hi = __floats2half2_rn(v.z, v.w);
        *(__half2*)(g_ench + i)     = lo;
        *(__half2*)(g_ench + i + 2) = hi;
    }
    {
        int b = bid >> 3, dc = bid & 7, d = dc * 256 + tid;
        const float* base = enc + (size_t)sloc[b] * Pp * Dd + d;
        float s0 = 0.f, s1 = 0.f, s2 = 0.f, s3 = 0.f;
        for (int p = 0; p < Pp; p += 4) {
            s0 += base[(size_t)p * Dd];
            s1 += base[(size_t)(p + 1) * Dd];
            s2 += base[(size_t)(p + 2) * Dd];
            s3 += base[(size_t)(p + 3) * Dd];
        }
        g_mean[b * Dd + d] = (s0 + s1 + s2 + s3) / 196.0f;
    }
}

// ---------------- skinny split-K body (f32x2, 32 rows) — init only ----------
__device__ __forceinline__ void skinny_body(const float* xs, const float* W,
                                            int st, int kPer,
                                            float* prow, int N) {
    ull acc[16];
#pragma unroll
    for (int i = 0; i < 16; i++) acc[i] = 0ULL;
    float w0 = W[0];
    float w1 = W[(size_t)st];
    float w2 = W[(size_t)2 * st];
    float w3 = W[(size_t)3 * st];
#pragma unroll 1
    for (int kk = 0; kk < kPer; kk += 4) {
        int kn = (kk + 4 < kPer) ? (kk + 4) : kk;
        float nw0 = W[(size_t)(kn + 0) * st];
        float nw1 = W[(size_t)(kn + 1) * st];
        float nw2 = W[(size_t)(kn + 2) * st];
        float nw3 = W[(size_t)(kn + 3) * st];
        const ulonglong2* x0 = (const ulonglong2*)(xs + (kk + 0) * 36);
        const ulonglong2* x1 = (const ulonglong2*)(xs + (kk + 1) * 36);
        const ulonglong2* x2 = (const ulonglong2*)(xs + (kk + 2) * 36);
        const ulonglong2* x3 = (const ulonglong2*)(xs + (kk + 3) * 36);
        ull wp;
        wp = pk2(w0);
#pragma unroll
        for (int i = 0; i < 8; i++) { ulonglong2 v = x0[i]; fm2(acc[2*i], v.x, wp); fm2(acc[2*i+1], v.y, wp); }
        wp = pk2(w1);
#pragma unroll
        for (int i = 0; i < 8; i++) { ulonglong2 v = x1[i]; fm2(acc[2*i], v.x, wp); fm2(acc[2*i+1], v.y, wp); }
        wp = pk2(w2);
#pragma unroll
        for (int i = 0; i < 8; i++) { ulonglong2 v = x2[i]; fm2(acc[2*i], v.x, wp); fm2(acc[2*i+1], v.y, wp); }
        wp = pk2(w3);
#pragma unroll
        for (int i = 0; i < 8; i++) { ulonglong2 v = x3[i]; fm2(acc[2*i], v.x, wp); fm2(acc[2*i+1], v.y, wp); }
        w0 = nw0; w1 = nw1; w2 = nw2; w3 = nw3;
    }
#pragma unroll
    for (int mp = 0; mp < 16; mp++) {
        float2 v = up2(acc[mp]);
        prow[(size_t)(2 * mp) * N]     = v.x;
        prow[(size_t)(2 * mp + 1) * N] = v.y;
    }
}

// ---------------- 32x64 tf32 MMA tile, double-buffered ----------------------
__device__ void mma32_tile(const float* xbase, int xstride, int kOff, int kLen,
                           const float* W0, const float* W1, int kSplit, int wst,
                           const float* WA, const float* WC, int mode,
                           int bn, float* pout, int N,
                           unsigned* As, unsigned* Bs) {
    int tid = threadIdx.x;
    int warp = tid >> 5, lane = tid & 31;
    int row = lane >> 2, tig = lane & 3;
    int wn = warp * 8;
    int arow = tid >> 3;
    int ak = (tid & 7) * 2;
    int bkk = tid >> 4;
    int bn4 = (tid & 15) * 4;

    float acc[2][4];
#pragma unroll
    for (int i = 0; i < 2; i++)
#pragma unroll
        for (int q = 0; q < 4; q++) acc[i][q] = 0.f;

    int nIter = kLen >> 4;
    auto stage = [&](int it, int buf) {
        const float* xp = xbase + (size_t)arow * xstride + kOff + it * 16 + ak;
        float2 xv = *(const float2*)xp;
        unsigned* A = As + buf * 544;
        A[arow * 17 + ak]     = tf32of(xv.x);
        A[arow * 17 + ak + 1] = tf32of(xv.y);
        int kg = kOff + it * 16 + bkk;
        const float* wp;
        if (mode == 0) {
            wp = (kg < kSplit) ? W0 + (size_t)kg * wst + bn + bn4
                               : W1 + (size_t)(kg - kSplit) * wst + bn + bn4;
        } else {
            int gn = bn + bn4;
            wp = (gn < 512) ? WA + (size_t)kg * 512 + gn
                            : WC + (size_t)kg * 2048 + (gn - 512);
        }
        float4 wv = *(const float4*)wp;
        unsigned* B = Bs + buf * 1088;
        B[(bn4 + 0) * 17 + bkk] = tf32of(wv.x);
        B[(bn4 + 1) * 17 + bkk] = tf32of(wv.y);
        B[(bn4 + 2) * 17 + bkk] = tf32of(wv.z);
        B[(bn4 + 3) * 17 + bkk] = tf32of(wv.w);
    };

    stage(0, 0);
    __syncthreads();
#pragma unroll 1
    for (int it = 0; it < nIter; it++) {
        int cur = it & 1;
        if (it + 1 < nIter) stage(it + 1, cur ^ 1);
        unsigned* A = As + cur * 544;
        unsigned* B = Bs + cur * 1088;
#pragma unroll
        for (int ks = 0; ks < 2; ks++) {
            int kb = ks * 8;
            unsigned b0 = B[(wn + row) * 17 + kb + tig];
            unsigned b1 = B[(wn + row) * 17 + kb + tig + 4];
#pragma unroll
            for (int mt = 0; mt < 2; mt++) {
                int m = mt * 16;
                unsigned a0 = A[(m + row) * 17 + kb + tig];
                unsigned a1 = A[(m + row + 8) * 17 + kb + tig];
                unsigned a2 = A[(m + row) * 17 + kb + tig + 4];
                unsigned a3 = A[(m + row + 8) * 17 + kb + tig + 4];
                mma_tf32(acc[mt], a0, a1, a2, a3, b0, b1);
            }
        }
        __syncthreads();
    }
#pragma unroll
    for (int mt = 0; mt < 2; mt++) {
        int m = mt * 16 + row;
        int n = bn + wn + 2 * tig;
        pout[(size_t)m * N + n]           = acc[mt][0];
        pout[(size_t)m * N + n + 1]       = acc[mt][1];
        pout[(size_t)(m + 8) * N + n]     = acc[mt][2];
        pout[(size_t)(m + 8) * N + n + 1] = acc[mt][3];
    }
}

// ---------------- tf32 tiles (att1/fc) ---------------------------------------
__device__ void att1_tile(int bx, int by,
                          const float* __restrict__ enc,
                          const float* __restrict__ W,
                          const float* __restrict__ bias,
                          unsigned* As, unsigned* Bs) {
    int tid = threadIdx.x;
    int warp = tid >> 5, lane = tid & 31;
    int bm = bx * 128, bn = by * 64;
    int wm = (warp & 3) * 32, wn = (warp >> 2) * 32;
    int row = lane >> 2, tig = lane & 3;
    int m0 = tid >> 2;
    int kq4 = (tid & 3) * 4;
    const float *arow0, *arow1;
    {
        int gm = bm + m0; int b = gm / 196, p = gm - b * 196;
        arow0 = enc + ((size_t)g_sort[b] * Pp + p) * Dd + kq4;
        gm = bm + m0 + 64; b = gm / 196; p = gm - b * 196;
        arow1 = enc + ((size_t)g_sort[b] * Pp + p) * Dd + kq4;
    }
    float acc[2][4][4];
#pragma unroll
    for (int i = 0; i < 2; i++)
#pragma unroll
        for (int j = 0; j < 4; j++)
#pragma unroll
            for (int q = 0; q < 4; q++) acc[i][j][q] = 0.f;

    for (int k0 = 0; k0 < Dd; k0 += 16) {
        float4 va = *(const float4*)(arow0 + k0);
        As[m0 * 37 + kq4 + 0] = tf32of(va.x);
        As[m0 * 37 + kq4 + 1] = tf32of(va.y);
        As[m0 * 37 + kq4 + 2] = tf32of(va.z);
        As[m0 * 37 + kq4 + 3] = tf32of(va.w);
        va = *(const float4*)(arow1 + k0);
        As[(m0 + 64) * 37 + kq4 + 0] = tf32of(va.x);
        As[(m0 + 64) * 37 + kq4 + 1] = tf32of(va.y);
        As[(m0 + 64) * 37 + kq4 + 2] = tf32of(va.z);
        As[(m0 + 64) * 37 + kq4 + 3] = tf32of(va.w);
#pragma unroll
        for (int i = 0; i < 4; i++) {
            int idx = tid + i * 256;
            int kk = idx >> 6, n = idx & 63;
            Bs[n * 21 + kk] = tf32of(W[(size_t)(k0 + kk) * Aa + bn + n]);
        }
        __syncthreads();
#pragma unroll
        for (int ks = 0; ks < 2; ks++) {
            int kb = ks * 8;
            unsigned b0[4], b1[4];
#pragma unroll
            for (int nt = 0; nt < 4; nt++) {
                int n = wn + nt * 8 + row;
                b0[nt] = Bs[n * 21 + kb + tig];
                b1[nt] = Bs[n * 21 + kb + tig + 4];
            }
#pragma unroll
            for (int mt = 0; mt < 2; mt++) {
                int m = wm + mt * 16;
                unsigned a0 = As[(m + row) * 37 + kb + tig];
                unsigned a1 = As[(m + row + 8) * 37 + kb + tig];
                unsigned a2 = As[(m + row) * 37 + kb + tig + 4];
                unsigned a3 = As[(m + row + 8) * 37 + kb + tig + 4];
#pragma unroll
                for (int nt = 0; nt < 4; nt++)
                    mma_tf32(acc[mt][nt], a0, a1, a2, a3, b0[nt], b1[nt]);
            }
        }
        __syncthreads();
    }
#pragma unroll
    for (int mt = 0; mt < 2; mt++) {
        int mrow = bm + wm + mt * 16 + row;
#pragma unroll
        for (int nt = 0; nt < 4; nt++) {
            int col = bn + wn + nt * 8 + 2 * tig;
            float b0v = bias[col], b1v = bias[col + 1];
            g_att1[(size_t)mrow * Aa + col]           = acc[mt][nt][0] + b0v;
            g_att1[(size_t)mrow * Aa + col + 1]       = acc[mt][nt][1] + b1v;
            g_att1[(size_t)(mrow + 8) * Aa + col]     = acc[mt][nt][2] + b0v;
            g_att1[(size_t)(mrow + 8) * Aa + col + 1] = acc[mt][nt][3] + b1v;
        }
    }
}

__device__ void fc_tile(int bx, int by,
                        const float* __restrict__ fc_w,
                        const float* __restrict__ fc_b,
                        float* __restrict__ out,
                        unsigned* As, unsigned* Bs) {
    int tid = threadIdx.x;
    int warp = tid >> 5, lane = tid & 31;
    int bm = bx * 128, bn = by * 64;
    int wm = (warp & 3) * 32, wn = (warp >> 2) * 32;
    int row = lane >> 2, tig = lane & 3;
    int m0 = tid >> 2;
    int kq4 = (tid & 3) * 4;
    const float* arow0 = g_hall + (size_t)(bm + m0) * Hh + kq4;
    const float* arow1 = g_hall + (size_t)(bm + m0 + 64) * Hh + kq4;

    float acc[2][4][4];
#pragma unroll
    for (int i = 0; i < 2; i++)
#pragma unroll
        for (int j = 0; j < 4; j++)
#pragma unroll
            for (int q = 0; q < 4; q++) acc[i][j][q] = 0.f;

    for (int k0 = 0; k0 < Hh; k0 += 16) {
        float4 va = *(const float4*)(arow0 + k0);
        As[m0 * 37 + kq4 + 0] = tf32of(va.x);
        As[m0 * 37 + kq4 + 1] = tf32of(va.y);
        As[m0 * 37 + kq4 + 2] = tf32of(va.z);
        As[m0 * 37 + kq4 + 3] = tf32of(va.w);
        va = *(const float4*)(arow1 + k0);
        As[(m0 + 64) * 37 + kq4 + 0] = tf32of(va.x);
        As[(m0 + 64) * 37 + kq4 + 1] = tf32of(va.y);
        As[(m0 + 64) * 37 + kq4 + 2] = tf32of(va.z);
        As[(m0 + 64) * 37 + kq4 + 3] = tf32of(va.w);
#pragma unroll
        for (int i = 0; i < 4; i++) {
            int idx = tid + i * 256;
            int kk = idx >> 6, n = idx & 63;
            int gn = bn + n;
            Bs[n * 21 + kk] = (gn < Vv) ? tf32of(fc_w[(size_t)(k0 + kk) * Vv + gn]) : 0u;
        }
        __syncthreads();
#pragma unroll
        for (int ks = 0; ks < 2; ks++) {
            int kb = ks * 8;
            unsigned b0[4], b1[4];
#pragma unroll
            for (int nt = 0; nt < 4; nt++) {
                int n = wn + nt * 8 + row;
                b0[nt] = Bs[n * 21 + kb + tig];
                b1[nt] = Bs[n * 21 + kb + tig + 4];
            }
#pragma unroll
            for (int mt = 0; mt < 2; mt++) {
                int m = wm + mt * 16;
                unsigned a0 = As[(m + row) * 37 + kb + tig];
                unsigned a1 = As[(m + row + 8) * 37 + kb + tig];
                unsigned a2 = As[(m + row) * 37 + kb + tig + 4];
                unsigned a3 = As[(m + row + 8) * 37 + kb + tig + 4];
#pragma unroll
                for (int nt = 0; nt < 4; nt++)
                    mma_tf32(acc[mt][nt], a0, a1, a2, a3, b0[nt], b1[nt]);
            }
        }
        __syncthreads();
    }
#pragma unroll
    for (int mt = 0; mt < 2; mt++) {
#pragma unroll
        for (int rr = 0; rr < 2; rr++) {
            int m = bm + wm + mt * 16 + row + rr * 8;
            int t = m >> 5, b = m & 31;
            int active = (t < g_declen[b]);
            size_t obase = OUT_PRED + ((size_t)b * Tt + t) * Vv;
#pragma unroll
            for (int nt = 0; nt < 4; nt++) {
                int col = bn + wn + nt * 8 + 2 * tig;
                if (col >= Vv) continue;
                float v0 = acc[mt][nt][2 * rr + 0];
                float v1 = acc[mt][nt][2 * rr + 1];
                out[obase + col] = active ? (v0 + fc_b[col]) : 0.f;
                if (col + 1 < Vv)
                    out[obase + col + 1] = active ? (v1 + fc_b[col + 1]) : 0.f;
            }
        }
    }
}

// ---------------- mega kernel ------------------------------------------------
__global__ void __launch_bounds__(256, 2) mega_kernel(
    const float* __restrict__ enc,
    const float* __restrict__ enc_att_w, const float* __restrict__ enc_att_b,
    const float* __restrict__ init_h_w,  const float* __restrict__ init_h_b,
    const float* __restrict__ init_c_w,  const float* __restrict__ init_c_b,
    const float* __restrict__ dec_att_w, const float* __restrict__ dec_att_b,
    const float* __restrict__ f_beta_w,  const float* __restrict__ f_beta_b,
    const float* __restrict__ full_w,    const float* __restrict__ full_b,
    const float* __restrict__ lstm_w_ih, const float* __restrict__ lstm_w_hh,
    const float* __restrict__ lstm_b,
    const float* __restrict__ fc_w,      const float* __restrict__ fc_b,
    float* __restrict__ out)
{
    __shared__ __align__(16) unsigned char SM[24832];
    __shared__ float red[16];
    unsigned* As = (unsigned*)SM;
    unsigned* Bs = (unsigned*)(SM + 18944);
    unsigned* As2 = (unsigned*)SM;                 // 2*544*4  = 4352B
    unsigned* Bs2 = (unsigned*)(SM + 4352);        // 2*1088*4 = 8704B
    float* xs  = (float*)SM;
    float* sbf = (float*)SM;

    const int bid = blockIdx.x, tid = threadIdx.x;
    const int warp = tid >> 5, lane = tid & 31;
    unsigned ph = 0;

    // ---- Phase A0: att1 tiles + init split-K parts -------------------------
    for (int vb = bid; vb < 392; vb += GRD)
        att1_tile(vb % 49, vb / 49, enc, enc_att_w, enc_att_b, As, Bs);
    for (int u = bid; u < 256; u += GRD) {
        int ky = u >> 2, nx = u & 3;
        int kBeg = ky * 32;
        __syncthreads();
        for (int i = tid; i < 32 * 32; i += 256) {
            int m = i >> 5, kk = i & 31;
            xs[kk * 36 + m] = g_mean[m * 2048 + kBeg + kk];
        }
        __syncthreads();
        int n = nx * 256 + tid;
        const float* W = (n < 512) ? (init_h_w + (size_t)kBeg * 512 + n)
                                   : (init_c_w + (size_t)kBeg * 512 + (n - 512));
        skinny_body(xs, W, 512, 32,
                    g_part + PART_B + (size_t)(ky * 32) * 1024 + n, 1024);
    }
    gsync(++ph);

    // ---- init reduce -> h0/c0 ----------------------------------------------
    if (bid < 128) {
        int idx = bid * 256 + tid;
        int m = idx >> 10, n = idx & 1023;
        float s0 = 0.f, s1 = 0.f;
#pragma unroll 8
        for (int ks = 0; ks < 64; ks += 2) {
            s0 += g_part[PART_B + ((size_t)(ks * 32 + m)) * 1024 + n];
            s1 += g_part[PART_B + ((size_t)((ks + 1) * 32 + m)) * 1024 + n];
        }
        float s = s0 + s1;
        if (n < 512) {
            float v = s + init_h_b[n];
            g_h[m * 512 + n] = v;
            g_x[m * 3072 + 2560 + n] = v;
        } else {
            g_c[m * 512 + (n - 512)] = s + init_c_b[n - 512];
        }
    }
    gsync(++ph);

    // ---- decode loop (R13 structure: 5 phases/step) -------------------------
    for (int t = 0; t < Tt; t++) {
        // PA: hproj via MMA: [att2|gate] = h @ [dec|f_beta], 40 n-tiles x KS4
        if (bid < 160) {
            int nx = bid % 40, ky = bid / 40;      // ky 0..3
            mma32_tile(g_h, 512, ky * 128, 128,
                       0, 0, 0, 0, dec_att_w, f_beta_w, 1,
                       nx * 64,
                       g_part + (size_t)(ky * 32) * 2560, 2560,
                       As2, Bs2);
        }
        gsync(++ph);

        // PB: attention scores -> g_escore (256 units)
        if (bid < 256) {
            int b = bid >> 3, pc = bid & 7;
#pragma unroll
            for (int rep = 0; rep < 2; rep++) {
                int aa = rep * 256 + tid;
                float s0 = dec_att_b[aa];
#pragma unroll
                for (int ks = 0; ks < 4; ks++)
                    s0 += g_part[(size_t)(ks * 32 + b) * 2560 + aa];
                sbf[aa] = s0;
                sbf[512 + aa] = full_w[aa];
            }
            __syncthreads();
            float fb = *full_b;
            int pbeg = pc * 25;
            int pend = min(196, pbeg + 25);
            for (int p = pbeg + warp; p < pend; p += 8) {
                const float4* rowp = (const float4*)(g_att1 + (size_t)(b * 196 + p) * 512);
                float s = 0.f;
#pragma unroll
                for (int a4 = lane; a4 < 128; a4 += 32) {
                    float4 v = rowp[a4];
                    float4 tt = *(const float4*)&sbf[a4 * 4];
                    float4 w = *(const float4*)&sbf[512 + a4 * 4];
                    s += fmaxf(v.x + tt.x, 0.f) * w.x;
                    s += fmaxf(v.y + tt.y, 0.f) * w.y;
                    s += fmaxf(v.z + tt.z, 0.f) * w.z;
                    s += fmaxf(v.w + tt.w, 0.f) * w.w;
                }
#pragma unroll
                for (int o = 16; o; o >>= 1) s += __shfl_down_sync(0xffffffffu, s, o);
                if (lane == 0) g_escore[b * 196 + p] = s + fb;
            }
        }
        gsync(++ph);

        // PC: softmax (redundant) + gate + awe (fp16 enc) -> x (256 units)
        if (bid < 256) {
            int b = bid >> 3, dc = bid & 7;
            float e = (tid < 196) ? g_escore[b * 196 + tid] : -FLT_MAX;
            float m = e;
#pragma unroll
            for (int o = 16; o; o >>= 1)
                m = fmaxf(m, __shfl_xor_sync(0xffffffffu, m, o));
            if (lane == 0) red[warp] = m;
            __syncthreads();
            if (tid == 0) {
                float mm = red[0];
#pragma unroll
                for (int i = 1; i < 8; i++) mm = fmaxf(mm, red[i]);
                red[8] = mm;
            }
            __syncthreads();
            float mx = red[8];
            float ex = (tid < 196) ? expf(e - mx) : 0.f;
            float ss = ex;
#pragma unroll
            for (int o = 16; o; o >>= 1) ss += __shfl_xor_sync(0xffffffffu, ss, o);
            if (lane == 0) red[warp] = ss;
            __syncthreads();
            if (tid == 0) {
                float s2 = 0.f;
#pragma unroll
                for (int i = 0; i < 8; i++) s2 += red[i];
                red[9] = s2;
            }
            __syncthreads();
            float inv = 1.f / red[9];
            if (tid < 196) sbf[tid] = ex * inv;
            __syncthreads();
            int active = (t < g_declen[b]);
            if (dc == 0 && tid < 196)
                out[OUT_ALPHA + (size_t)(b * Tt + t) * 196 + tid] =
                    active ? sbf[tid] : 0.f;
            int d = dc * 256 + tid;
            float gp = f_beta_b[d];
#pragma unroll
            for (int ks = 0; ks < 4; ks++)
                gp += g_part[(size_t)(ks * 32 + b) * 2560 + 512 + d];
            float gate = sigf(gp);
            const __half* baseh = g_ench + (size_t)b * Pp * Dd + d;
            float acc8[8];
#pragma unroll
            for (int i = 0; i < 8; i++) acc8[i] = 0.f;
#pragma unroll 1
            for (int p = 0; p < 192; p += 8) {
#pragma unroll
                for (int i = 0; i < 8; i++)
                    acc8[i] += __half2float(baseh[(size_t)(p + i) * Dd]) * sbf[p + i];
            }
#pragma unroll
            for (int i = 0; i < 4; i++)
                acc8[i] += __half2float(baseh[(size_t)(192 + i) * Dd]) * sbf[192 + i];
            float s = ((acc8[0] + acc8[1]) + (acc8[2] + acc8[3])) +
                      ((acc8[4] + acc8[5]) + (acc8[6] + acc8[7]));
            g_x[b * 3072 + 512 + d] = s * gate;
        }
        gsync(++ph);

        // PD: full lstm gates via MMA: x[32,3072] @ W, 32 n-tiles x KS8
        if (bid < 256) {
            int nx = bid & 31, ky = bid >> 5;     // ky 0..7, k-chunk 384
            mma32_tile(g_x, 3072, ky * 384, 384,
                       lstm_w_ih, lstm_w_hh, 2560, 2048, 0, 0, 0,
                       nx * 64,
                       g_part + PART_B + (size_t)(ky * 32) * 2048, 2048,
                       As2, Bs2);
        }
        gsync(++ph);

        // PE: LSTM cell (64 units), KS=8
        if (bid < 64) {
            int idx = bid * 256 + tid;
            int b = idx >> 9, j = idx & 511;
            float s[4];
#pragma unroll
            for (int g = 0; g < 4; g++) s[g] = lstm_b[g * 512 + j];
#pragma unroll
            for (int ks = 0; ks < 8; ks++) {
                size_t base0 = PART_B + (size_t)(ks * 32 + b) * 2048 + j;
#pragma unroll
                for (int g = 0; g < 4; g++)
                    s[g] += g_part[base0 + g * 512];
            }
            float c_old = g_c[idx];
            float c_new = sigf(s[1]) * c_old + sigf(s[0]) * tanhf(s[2]);
            float h_new = sigf(s[3]) * tanhf(c_new);
            g_hall[((size_t)t * Bt + b) * Hh + j] = h_new;
            int active = (t < g_declen[b]);
            float h_keep = active ? h_new : g_h[idx];
            float c_keep = active ? c_new : c_old;
            g_h[idx] = h_keep;
            g_c[idx] = c_keep;
            g_x[b * 3072 + 2560 + j] = h_keep;
            if (t + 1 < Tt)
                g_x[b * 3072 + j] = g_embs[((size_t)b * Tt + (t + 1)) * Ee + j];
        }
        gsync(++ph);
    }

    // ---- FC: preds = h_all @ fc_w + b (785 tiles) ---------------------------
    for (int vb = bid; vb < 785; vb += GRD)
        fc_tile(vb % 5, vb / 5, fc_w, fc_b, out, As, Bs);
}

// ---------------- launch ----------------------------------------------------
extern "C" void kernel_launch(void* const* d_in, const int* in_sizes, int n_in,
                              void* d_out, int out_size) {
    const float* enc        = (const float*)d_in[0];
    const int*   caps_in    = (const int*)d_in[1];
    const int*   caplen     = (const int*)d_in[2];
    const float* enc_att_w  = (const float*)d_in[3];
    const float* enc_att_b  = (const float*)d_in[4];
    const float* dec_att_w  = (const float*)d_in[5];
    const float* dec_att_b  = (const float*)d_in[6];
    const float* full_att_w = (const float*)d_in[7];
    const float* full_att_b = (const float*)d_in[8];
    const float* emb        = (const float*)d_in[9];
    const float* init_h_w   = (const float*)d_in[10];
    const float* init_h_b   = (const float*)d_in[11];
    const float* init_c_w   = (const float*)d_in[12];
    const float* init_c_b   = (const float*)d_in[13];
    const float* f_beta_w   = (const float*)d_in[14];
    const float* f_beta_b   = (const float*)d_in[15];
    const float* lstm_w_ih  = (const float*)d_in[16];
    const float* lstm_w_hh  = (const float*)d_in[17];
    const float* lstm_b     = (const float*)d_in[18];
    const float* fc_w       = (const float*)d_in[19];
    const float* fc_b       = (const float*)d_in[20];
    float* out = (float*)d_out;

    prep_kernel<<<256, 256>>>(caplen, caps_in, emb, enc, out);
    mega_kernel<<<GRD, 256>>>(enc,
                              enc_att_w, enc_att_b,
                              init_h_w, init_h_b,
                              init_c_w, init_c_b,
                              dec_att_w, dec_att_b,
                              f_beta_w, f_beta_b,
                              full_att_w, full_att_b,
                              lstm_w_ih, lstm_w_hh, lstm_b,
                              fc_w, fc_b,
                              out);
}

// round 17
// speedup vs baseline: 1.5466x; 1.0058x over previous
#include <cuda_runtime.h>
#include <cuda_fp16.h>
#include <math.h>
#include <float.h>

#define Bt 32
#define Pp 196
#define Dd 2048
#define Aa 512
#define Ee 512
#define Hh 512
#define Vv 10000
#define Ll 21
#define Tt 20
#define GRD 296

// output layout (float32, concatenated in return-tuple order)
#define OUT_PRED   0
#define OUT_CAPS   6400000
#define OUT_DECLEN 6400672
#define OUT_ALPHA  6400704
#define OUT_SORT   6526144

// g_part regions
#define PART_B 1310720   // lstm partials [8][32][2048]; init reuses [64][32][1024]

typedef unsigned long long ull;

// ---------------- packed f32x2 helpers --------------------------------------
__device__ __forceinline__ ull pk2(float x) {
    ull r; asm("mov.b64 %0, {%1, %1};" : "=l"(r) : "f"(x)); return r;
}
__device__ __forceinline__ void fm2(ull& d, ull a, ull b) {
    asm("fma.rn.f32x2 %0, %1, %2, %0;" : "+l"(d) : "l"(a), "l"(b));
}
__device__ __forceinline__ float2 up2(ull v) {
    float2 r; asm("mov.b64 {%0, %1}, %2;" : "=f"(r.x), "=f"(r.y) : "l"(v)); return r;
}

// ---------------- tf32 mma helpers ------------------------------------------
__device__ __forceinline__ unsigned tf32of(float x) {
    unsigned r; asm("cvt.rna.tf32.f32 %0, %1;" : "=r"(r) : "f"(x)); return r;
}
__device__ __forceinline__ void mma_tf32(float* c, unsigned a0, unsigned a1,
                                         unsigned a2, unsigned a3,
                                         unsigned b0, unsigned b1) {
    asm("mma.sync.aligned.m16n8k8.row.col.f32.tf32.tf32.f32 "
        "{%0,%1,%2,%3}, {%4,%5,%6,%7}, {%8,%9}, {%0,%1,%2,%3};"
        : "+f"(c[0]), "+f"(c[1]), "+f"(c[2]), "+f"(c[3])
        : "r"(a0), "r"(a1), "r"(a2), "r"(a3), "r"(b0), "r"(b1));
}

// ---------------- scratch (device globals; no runtime allocation) ----------
__device__ int   g_sort[Bt];
__device__ int   g_declen[Bt];
__device__ float g_mean[Bt * Dd];
__device__ float g_h[Bt * Hh];
__device__ float g_c[Bt * Hh];
__device__ float g_att1[Bt * Pp * Aa];       // 12.8 MB (fp32)
__device__ __half g_ench[Bt * Pp * Dd];      // 25.6 MB sorted enc, fp16
__device__ float g_escore[Bt * Pp];
__device__ float g_x[Bt * 3072];             // [emb | awe | h]
__device__ float g_embs[Bt * Tt * Ee];
__device__ float g_hall[Tt * Bt * Hh];
__device__ float g_part[4460000];            // split-K partials (2 regions)
__device__ __align__(128) unsigned g_arrive;
__device__ __align__(128) unsigned g_release;
__device__ unsigned g_sub1[Bt];              // per-b sub-barrier counters

__device__ __forceinline__ float sigf(float x) { return 1.0f / (1.0f + expf(-x)); }

// ---------------- two-line grid barrier --------------------------------------
__device__ __forceinline__ void gsync(unsigned ph) {
    __syncthreads();
    if (threadIdx.x == 0) {
        __threadfence();
        unsigned old = atomicAdd(&g_arrive, 1u);
        if (old == ph * GRD - 1u) {
            atomicExch(&g_release, ph);
        } else {
            while (*((volatile unsigned*)&g_release) < ph) { }
        }
        __threadfence();
    }
    __syncthreads();
}

// ---------------- prep: argsort + emb gather + mean + enc fp16 copy ---------
__global__ void __launch_bounds__(256) prep_kernel(
    const int* __restrict__ caplen, const int* __restrict__ caps_in,
    const float* __restrict__ emb,  const float* __restrict__ enc,
    float* __restrict__ out)
{
    __shared__ int len[Bt];
    __shared__ int sloc[Bt];
    int tid = threadIdx.x, bid = blockIdx.x;
    if (tid < Bt) len[tid] = caplen[tid];
    __syncthreads();
    if (tid < Bt) {
        int myl = len[tid], rank = 0;
        for (int j = 0; j < Bt; j++) {
            int lj = len[j];
            if (lj > myl || (lj == myl && j < tid)) rank++;
        }
        sloc[rank] = tid;
    }
    __syncthreads();
    if (bid == 0) {
        if (tid < Bt) {
            int sb = sloc[tid], dl = len[sb] - 1;
            g_sort[tid] = sb; g_declen[tid] = dl;
            out[OUT_SORT + tid]   = (float)sb;
            out[OUT_DECLEN + tid] = (float)dl;
            for (int l = 0; l < Ll; l++)
                out[OUT_CAPS + tid * Ll + l] = (float)caps_in[sb * Ll + l];
            g_sub1[tid] = 0u;
        }
        if (tid == 0) { g_arrive = 0u; g_release = 0u; }
    }
    for (int i = bid * 256 + tid; i < Bt * Tt * Ee; i += 256 * 256) {
        int b = i / (Tt * Ee);
        int r = i - b * (Tt * Ee);
        int t = r >> 9, j = r & 511;
        int tok = caps_in[sloc[b] * Ll + t];
        float v = emb[(size_t)tok * Ee + j];
        g_embs[i] = v;
        if (t == 0) g_x[b * 3072 + j] = v;
    }
    for (int i4 = bid * 256 + tid; i4 < Bt * Pp * Dd / 4; i4 += 256 * 256) {
        int i = i4 * 4;
        int b = i / (Pp * Dd);
        int r = i - b * (Pp * Dd);
        float4 v = *(const float4*)(enc + (size_t)sloc[b] * Pp * Dd + r);
        __half2 lo = __floats2half2_rn(v.x, v.y);
        __half2 hi = __floats2half2_rn(v.z, v.w);
        *(__half2*)(g_ench + i)     = lo;
        *(__half2*)(g_ench + i + 2) = hi;
    }
    {
        int b = bid >> 3, dc = bid & 7, d = dc * 256 + tid;
        const float* base = enc + (size_t)sloc[b] * Pp * Dd + d;
        float s0 = 0.f, s1 = 0.f, s2 = 0.f, s3 = 0.f;
        for (int p = 0; p < Pp; p += 4) {
            s0 += base[(size_t)p * Dd];
            s1 += base[(size_t)(p + 1) * Dd];
            s2 += base[(size_t)(p + 2) * Dd];
            s3 += base[(size_t)(p + 3) * Dd];
        }
        g_mean[b * Dd + d] = (s0 + s1 + s2 + s3) / 196.0f;
    }
}

// ---------------- skinny split-K body (f32x2, 32 rows) — init only ----------
__device__ __forceinline__ void skinny_body(const float* xs, const float* W,
                                            int st, int kPer,
                                            float* prow, int N) {
    ull acc[16];
#pragma unroll
    for (int i = 0; i < 16; i++) acc[i] = 0ULL;
    float w0 = W[0];
    float w1 = W[(size_t)st];
    float w2 = W[(size_t)2 * st];
    float w3 = W[(size_t)3 * st];
#pragma unroll 1
    for (int kk = 0; kk < kPer; kk += 4) {
        int kn = (kk + 4 < kPer) ? (kk + 4) : kk;
        float nw0 = W[(size_t)(kn + 0) * st];
        float nw1 = W[(size_t)(kn + 1) * st];
        float nw2 = W[(size_t)(kn + 2) * st];
        float nw3 = W[(size_t)(kn + 3) * st];
        const ulonglong2* x0 = (const ulonglong2*)(xs + (kk + 0) * 36);
        const ulonglong2* x1 = (const ulonglong2*)(xs + (kk + 1) * 36);
        const ulonglong2* x2 = (const ulonglong2*)(xs + (kk + 2) * 36);
        const ulonglong2* x3 = (const ulonglong2*)(xs + (kk + 3) * 36);
        ull wp;
        wp = pk2(w0);
#pragma unroll
        for (int i = 0; i < 8; i++) { ulonglong2 v = x0[i]; fm2(acc[2*i], v.x, wp); fm2(acc[2*i+1], v.y, wp); }
        wp = pk2(w1);
#pragma unroll
        for (int i = 0; i < 8; i++) { ulonglong2 v = x1[i]; fm2(acc[2*i], v.x, wp); fm2(acc[2*i+1], v.y, wp); }
        wp = pk2(w2);
#pragma unroll
        for (int i = 0; i < 8; i++) { ulonglong2 v = x2[i]; fm2(acc[2*i], v.x, wp); fm2(acc[2*i+1], v.y, wp); }
        wp = pk2(w3);
#pragma unroll
        for (int i = 0; i < 8; i++) { ulonglong2 v = x3[i]; fm2(acc[2*i], v.x, wp); fm2(acc[2*i+1], v.y, wp); }
        w0 = nw0; w1 = nw1; w2 = nw2; w3 = nw3;
    }
#pragma unroll
    for (int mp = 0; mp < 16; mp++) {
        float2 v = up2(acc[mp]);
        prow[(size_t)(2 * mp) * N]     = v.x;
        prow[(size_t)(2 * mp + 1) * N] = v.y;
    }
}

// ---------------- 32x64 tf32 MMA tile, double-buffered ----------------------
__device__ void mma32_tile(const float* xbase, int xstride, int kOff, int kLen,
                           const float* W0, const float* W1, int kSplit, int wst,
                           const float* WA, const float* WC, int mode,
                           int bn, float* pout, int N,
                           unsigned* As, unsigned* Bs) {
    int tid = threadIdx.x;
    int warp = tid >> 5, lane = tid & 31;
    int row = lane >> 2, tig = lane & 3;
    int wn = warp * 8;
    int arow = tid >> 3;
    int ak = (tid & 7) * 2;
    int bkk = tid >> 4;
    int bn4 = (tid & 15) * 4;

    float acc[2][4];
#pragma unroll
    for (int i = 0; i < 2; i++)
#pragma unroll
        for (int q = 0; q < 4; q++) acc[i][q] = 0.f;

    int nIter = kLen >> 4;
    auto stage = [&](int it, int buf) {
        const float* xp = xbase + (size_t)arow * xstride + kOff + it * 16 + ak;
        float2 xv = *(const float2*)xp;
        unsigned* A = As + buf * 544;
        A[arow * 17 + ak]     = tf32of(xv.x);
        A[arow * 17 + ak + 1] = tf32of(xv.y);
        int kg = kOff + it * 16 + bkk;
        const float* wp;
        if (mode == 0) {
            wp = (kg < kSplit) ? W0 + (size_t)kg * wst + bn + bn4
                               : W1 + (size_t)(kg - kSplit) * wst + bn + bn4;
        } else {
            int gn = bn + bn4;
            wp = (gn < 512) ? WA + (size_t)kg * 512 + gn
                            : WC + (size_t)kg * 2048 + (gn - 512);
        }
        float4 wv = *(const float4*)wp;
        unsigned* B = Bs + buf * 1088;
        B[(bn4 + 0) * 17 + bkk] = tf32of(wv.x);
        B[(bn4 + 1) * 17 + bkk] = tf32of(wv.y);
        B[(bn4 + 2) * 17 + bkk] = tf32of(wv.z);
        B[(bn4 + 3) * 17 + bkk] = tf32of(wv.w);
    };

    stage(0, 0);
    __syncthreads();
#pragma unroll 1
    for (int it = 0; it < nIter; it++) {
        int cur = it & 1;
        if (it + 1 < nIter) stage(it + 1, cur ^ 1);
        unsigned* A = As + cur * 544;
        unsigned* B = Bs + cur * 1088;
#pragma unroll
        for (int ks = 0; ks < 2; ks++) {
            int kb = ks * 8;
            unsigned b0 = B[(wn + row) * 17 + kb + tig];
            unsigned b1 = B[(wn + row) * 17 + kb + tig + 4];
#pragma unroll
            for (int mt = 0; mt < 2; mt++) {
                int m = mt * 16;
                unsigned a0 = A[(m + row) * 17 + kb + tig];
                unsigned a1 = A[(m + row + 8) * 17 + kb + tig];
                unsigned a2 = A[(m + row) * 17 + kb + tig + 4];
                unsigned a3 = A[(m + row + 8) * 17 + kb + tig + 4];
                mma_tf32(acc[mt], a0, a1, a2, a3, b0, b1);
            }
        }
        __syncthreads();
    }
#pragma unroll
    for (int mt = 0; mt < 2; mt++) {
        int m = mt * 16 + row;
        int n = bn + wn + 2 * tig;
        pout[(size_t)m * N + n]           = acc[mt][0];
        pout[(size_t)m * N + n + 1]       = acc[mt][1];
        pout[(size_t)(m + 8) * N + n]     = acc[mt][2];
        pout[(size_t)(m + 8) * N + n + 1] = acc[mt][3];
    }
}

// ---------------- tf32 tiles (att1/fc) ---------------------------------------
__device__ void att1_tile(int bx, int by,
                          const float* __restrict__ enc,
                          const float* __restrict__ W,
                          const float* __restrict__ bias,
                          unsigned* As, unsigned* Bs) {
    int tid = threadIdx.x;
    int warp = tid >> 5, lane = tid & 31;
    int bm = bx * 128, bn = by * 64;
    int wm = (warp & 3) * 32, wn = (warp >> 2) * 32;
    int row = lane >> 2, tig = lane & 3;
    int m0 = tid >> 2;
    int kq4 = (tid & 3) * 4;
    const float *arow0, *arow1;
    {
        int gm = bm + m0; int b = gm / 196, p = gm - b * 196;
        arow0 = enc + ((size_t)g_sort[b] * Pp + p) * Dd + kq4;
        gm = bm + m0 + 64; b = gm / 196; p = gm - b * 196;
        arow1 = enc + ((size_t)g_sort[b] * Pp + p) * Dd + kq4;
    }
    float acc[2][4][4];
#pragma unroll
    for (int i = 0; i < 2; i++)
#pragma unroll
        for (int j = 0; j < 4; j++)
#pragma unroll
            for (int q = 0; q < 4; q++) acc[i][j][q] = 0.f;

    for (int k0 = 0; k0 < Dd; k0 += 16) {
        float4 va = *(const float4*)(arow0 + k0);
        As[m0 * 37 + kq4 + 0] = tf32of(va.x);
        As[m0 * 37 + kq4 + 1] = tf32of(va.y);
        As[m0 * 37 + kq4 + 2] = tf32of(va.z);
        As[m0 * 37 + kq4 + 3] = tf32of(va.w);
        va = *(const float4*)(arow1 + k0);
        As[(m0 + 64) * 37 + kq4 + 0] = tf32of(va.x);
        As[(m0 + 64) * 37 + kq4 + 1] = tf32of(va.y);
        As[(m0 + 64) * 37 + kq4 + 2] = tf32of(va.z);
        As[(m0 + 64) * 37 + kq4 + 3] = tf32of(va.w);
#pragma unroll
        for (int i = 0; i < 4; i++) {
            int idx = tid + i * 256;
            int kk = idx >> 6, n = idx & 63;
            Bs[n * 21 + kk] = tf32of(W[(size_t)(k0 + kk) * Aa + bn + n]);
        }
        __syncthreads();
#pragma unroll
        for (int ks = 0; ks < 2; ks++) {
            int kb = ks * 8;
            unsigned b0[4], b1[4];
#pragma unroll
            for (int nt = 0; nt < 4; nt++) {
                int n = wn + nt * 8 + row;
                b0[nt] = Bs[n * 21 + kb + tig];
                b1[nt] = Bs[n * 21 + kb + tig + 4];
            }
#pragma unroll
            for (int mt = 0; mt < 2; mt++) {
                int m = wm + mt * 16;
                unsigned a0 = As[(m + row) * 37 + kb + tig];
                unsigned a1 = As[(m + row + 8) * 37 + kb + tig];
                unsigned a2 = As[(m + row) * 37 + kb + tig + 4];
                unsigned a3 = As[(m + row + 8) * 37 + kb + tig + 4];
#pragma unroll
                for (int nt = 0; nt < 4; nt++)
                    mma_tf32(acc[mt][nt], a0, a1, a2, a3, b0[nt], b1[nt]);
            }
        }
        __syncthreads();
    }
#pragma unroll
    for (int mt = 0; mt < 2; mt++) {
        int mrow = bm + wm + mt * 16 + row;
#pragma unroll
        for (int nt = 0; nt < 4; nt++) {
            int col = bn + wn + nt * 8 + 2 * tig;
            float b0v = bias[col], b1v = bias[col + 1];
            g_att1[(size_t)mrow * Aa + col]           = acc[mt][nt][0] + b0v;
            g_att1[(size_t)mrow * Aa + col + 1]       = acc[mt][nt][1] + b1v;
            g_att1[(size_t)(mrow + 8) * Aa + col]     = acc[mt][nt][2] + b0v;
            g_att1[(size_t)(mrow + 8) * Aa + col + 1] = acc[mt][nt][3] + b1v;
        }
    }
}

__device__ void fc_tile(int bx, int by,
                        const float* __restrict__ fc_w,
                        const float* __restrict__ fc_b,
                        float* __restrict__ out,
                        unsigned* As, unsigned* Bs) {
    int tid = threadIdx.x;
    int warp = tid >> 5, lane = tid & 31;
    int bm = bx * 128, bn = by * 64;
    int wm = (warp & 3) * 32, wn = (warp >> 2) * 32;
    int row = lane >> 2, tig = lane & 3;
    int m0 = tid >> 2;
    int kq4 = (tid & 3) * 4;
    const float* arow0 = g_hall + (size_t)(bm + m0) * Hh + kq4;
    const float* arow1 = g_hall + (size_t)(bm + m0 + 64) * Hh + kq4;

    float acc[2][4][4];
#pragma unroll
    for (int i = 0; i < 2; i++)
#pragma unroll
        for (int j = 0; j < 4; j++)
#pragma unroll
            for (int q = 0; q < 4; q++) acc[i][j][q] = 0.f;

    for (int k0 = 0; k0 < Hh; k0 += 16) {
        float4 va = *(const float4*)(arow0 + k0);
        As[m0 * 37 + kq4 + 0] = tf32of(va.x);
        As[m0 * 37 + kq4 + 1] = tf32of(va.y);
        As[m0 * 37 + kq4 + 2] = tf32of(va.z);
        As[m0 * 37 + kq4 + 3] = tf32of(va.w);
        va = *(const float4*)(arow1 + k0);
        As[(m0 + 64) * 37 + kq4 + 0] = tf32of(va.x);
        As[(m0 + 64) * 37 + kq4 + 1] = tf32of(va.y);
        As[(m0 + 64) * 37 + kq4 + 2] = tf32of(va.z);
        As[(m0 + 64) * 37 + kq4 + 3] = tf32of(va.w);
#pragma unroll
        for (int i = 0; i < 4; i++) {
            int idx = tid + i * 256;
            int kk = idx >> 6, n = idx & 63;
            int gn = bn + n;
            Bs[n * 21 + kk] = (gn < Vv) ? tf32of(fc_w[(size_t)(k0 + kk) * Vv + gn]) : 0u;
        }
        __syncthreads();
#pragma unroll
        for (int ks = 0; ks < 2; ks++) {
            int kb = ks * 8;
            unsigned b0[4], b1[4];
#pragma unroll
            for (int nt = 0; nt < 4; nt++) {
                int n = wn + nt * 8 + row;
                b0[nt] = Bs[n * 21 + kb + tig];
                b1[nt] = Bs[n * 21 + kb + tig + 4];
            }
#pragma unroll
            for (int mt = 0; mt < 2; mt++) {
                int m = wm + mt * 16;
                unsigned a0 = As[(m + row) * 37 + kb + tig];
                unsigned a1 = As[(m + row + 8) * 37 + kb + tig];
                unsigned a2 = As[(m + row) * 37 + kb + tig + 4];
                unsigned a3 = As[(m + row + 8) * 37 + kb + tig + 4];
#pragma unroll
                for (int nt = 0; nt < 4; nt++)
                    mma_tf32(acc[mt][nt], a0, a1, a2, a3, b0[nt], b1[nt]);
            }
        }
        __syncthreads();
    }
#pragma unroll
    for (int mt = 0; mt < 2; mt++) {
#pragma unroll
        for (int rr = 0; rr < 2; rr++) {
            int m = bm + wm + mt * 16 + row + rr * 8;
            int t = m >> 5, b = m & 31;
            int active = (t < g_declen[b]);
            size_t obase = OUT_PRED + ((size_t)b * Tt + t) * Vv;
#pragma unroll
            for (int nt = 0; nt < 4; nt++) {
                int col = bn + wn + nt * 8 + 2 * tig;
                if (col >= Vv) continue;
                float v0 = acc[mt][nt][2 * rr + 0];
                float v1 = acc[mt][nt][2 * rr + 1];
                out[obase + col] = active ? (v0 + fc_b[col]) : 0.f;
                if (col + 1 < Vv)
                    out[obase + col + 1] = active ? (v1 + fc_b[col + 1]) : 0.f;
            }
        }
    }
}

// ---------------- mega kernel ------------------------------------------------
__global__ void __launch_bounds__(256, 2) mega_kernel(
    const float* __restrict__ enc,
    const float* __restrict__ enc_att_w, const float* __restrict__ enc_att_b,
    const float* __restrict__ init_h_w,  const float* __restrict__ init_h_b,
    const float* __restrict__ init_c_w,  const float* __restrict__ init_c_b,
    const float* __restrict__ dec_att_w, const float* __restrict__ dec_att_b,
    const float* __restrict__ f_beta_w,  const float* __restrict__ f_beta_b,
    const float* __restrict__ full_w,    const float* __restrict__ full_b,
    const float* __restrict__ lstm_w_ih, const float* __restrict__ lstm_w_hh,
    const float* __restrict__ lstm_b,
    const float* __restrict__ fc_w,      const float* __restrict__ fc_b,
    float* __restrict__ out)
{
    __shared__ __align__(16) unsigned char SM[24832];
    __shared__ float red[16];
    unsigned* As = (unsigned*)SM;
    unsigned* Bs = (unsigned*)(SM + 18944);
    unsigned* As2 = (unsigned*)SM;                 // 2*544*4  = 4352B
    unsigned* Bs2 = (unsigned*)(SM + 4352);        // 2*1088*4 = 8704B
    float* xs  = (float*)SM;
    float* sbf = (float*)SM;

    const int bid = blockIdx.x, tid = threadIdx.x;
    const int warp = tid >> 5, lane = tid & 31;
    unsigned ph = 0;

    // ---- Phase A0: att1 tiles + init split-K parts -------------------------
    for (int vb = bid; vb < 392; vb += GRD)
        att1_tile(vb % 49, vb / 49, enc, enc_att_w, enc_att_b, As, Bs);
    for (int u = bid; u < 256; u += GRD) {
        int ky = u >> 2, nx = u & 3;
        int kBeg = ky * 32;
        __syncthreads();
        for (int i = tid; i < 32 * 32; i += 256) {
            int m = i >> 5, kk = i & 31;
            xs[kk * 36 + m] = g_mean[m * 2048 + kBeg + kk];
        }
        __syncthreads();
        int n = nx * 256 + tid;
        const float* W = (n < 512) ? (init_h_w + (size_t)kBeg * 512 + n)
                                   : (init_c_w + (size_t)kBeg * 512 + (n - 512));
        skinny_body(xs, W, 512, 32,
                    g_part + PART_B + (size_t)(ky * 32) * 1024 + n, 1024);
    }
    gsync(++ph);

    // ---- init reduce -> h0/c0 ----------------------------------------------
    if (bid < 128) {
        int idx = bid * 256 + tid;
        int m = idx >> 10, n = idx & 1023;
        float s0 = 0.f, s1 = 0.f;
#pragma unroll 8
        for (int ks = 0; ks < 64; ks += 2) {
            s0 += g_part[PART_B + ((size_t)(ks * 32 + m)) * 1024 + n];
            s1 += g_part[PART_B + ((size_t)((ks + 1) * 32 + m)) * 1024 + n];
        }
        float s = s0 + s1;
        if (n < 512) {
            float v = s + init_h_b[n];
            g_h[m * 512 + n] = v;
            g_x[m * 3072 + 2560 + n] = v;
        } else {
            g_c[m * 512 + (n - 512)] = s + init_c_b[n - 512];
        }
    }
    gsync(++ph);

    // ---- decode loop: 4 full barriers/step ----------------------------------
    for (int t = 0; t < Tt; t++) {
        // PA: hproj via MMA: [att2|gate] = h @ [dec|f_beta], 40 n-tiles x KS4
        if (bid < 160) {
            int nx = bid % 40, ky = bid / 40;      // ky 0..3
            mma32_tile(g_h, 512, ky * 128, 128,
                       0, 0, 0, 0, dec_att_w, f_beta_w, 1,
                       nx * 64,
                       g_part + (size_t)(ky * 32) * 2560, 2560,
                       As2, Bs2);
        }
        gsync(++ph);

        // PBC: scores (chunk i) -> per-b sub-barrier -> softmax + gate + awe
        if (bid < 256) {
            int b = bid >> 3, i = bid & 7;
            // att2 reduce (KS=4) + full_w into smem
#pragma unroll
            for (int rep = 0; rep < 2; rep++) {
                int aa = rep * 256 + tid;
                float s0 = dec_att_b[aa];
#pragma unroll
                for (int ks = 0; ks < 4; ks++)
                    s0 += g_part[(size_t)(ks * 32 + b) * 2560 + aa];
                sbf[aa] = s0;
                sbf[512 + aa] = full_w[aa];
            }
            __syncthreads();
            float fb = *full_b;
            int pbeg = i * 25;
            int pend = min(196, pbeg + 25);
            for (int p = pbeg + warp; p < pend; p += 8) {
                const float4* rowp = (const float4*)(g_att1 + (size_t)(b * 196 + p) * 512);
                float s = 0.f;
#pragma unroll
                for (int a4 = lane; a4 < 128; a4 += 32) {
                    float4 v = rowp[a4];
                    float4 tt = *(const float4*)&sbf[a4 * 4];
                    float4 w = *(const float4*)&sbf[512 + a4 * 4];
                    s += fmaxf(v.x + tt.x, 0.f) * w.x;
                    s += fmaxf(v.y + tt.y, 0.f) * w.y;
                    s += fmaxf(v.z + tt.z, 0.f) * w.z;
                    s += fmaxf(v.w + tt.w, 0.f) * w.w;
                }
#pragma unroll
                for (int o = 16; o; o >>= 1) s += __shfl_down_sync(0xffffffffu, s, o);
                if (lane == 0) g_escore[b * 196 + p] = s + fb;
            }
            // sub-barrier: the 8 blocks of this b rendezvous
            __syncthreads();
            if (tid == 0) {
                __threadfence();
                atomicAdd(&g_sub1[b], 1u);
                while (*((volatile unsigned*)&g_sub1[b]) < 8u * (t + 1)) { }
                __threadfence();
            }
            __syncthreads();
            // softmax (redundant per block)
            float e = (tid < 196) ? g_escore[b * 196 + tid] : -FLT_MAX;
            float m = e;
#pragma unroll
            for (int o = 16; o; o >>= 1)
                m = fmaxf(m, __shfl_xor_sync(0xffffffffu, m, o));
            if (lane == 0) red[warp] = m;
            __syncthreads();
            if (tid == 0) {
                float mm = red[0];
#pragma unroll
                for (int q = 1; q < 8; q++) mm = fmaxf(mm, red[q]);
                red[8] = mm;
            }
            __syncthreads();
            float mx = red[8];
            float ex = (tid < 196) ? expf(e - mx) : 0.f;
            float ss = ex;
#pragma unroll
            for (int o = 16; o; o >>= 1) ss += __shfl_xor_sync(0xffffffffu, ss, o);
            if (lane == 0) red[warp] = ss;
            __syncthreads();
            if (tid == 0) {
                float s2 = 0.f;
#pragma unroll
                for (int q = 0; q < 8; q++) s2 += red[q];
                red[9] = s2;
            }
            __syncthreads();
            float inv = 1.f / red[9];
            if (tid < 196) sbf[tid] = ex * inv;   // alpha (att2 region reusable now)
            __syncthreads();
            int active = (t < g_declen[b]);
            if (i == 0 && tid < 196)
                out[OUT_ALPHA + (size_t)(b * Tt + t) * 196 + tid] =
                    active ? sbf[tid] : 0.f;
            int d = i * 256 + tid;
            float gp = f_beta_b[d];
#pragma unroll
            for (int ks = 0; ks < 4; ks++)
                gp += g_part[(size_t)(ks * 32 + b) * 2560 + 512 + d];
            float gate = sigf(gp);
            const __half* baseh = g_ench + (size_t)b * Pp * Dd + d;
            float acc8[8];
#pragma unroll
            for (int q = 0; q < 8; q++) acc8[q] = 0.f;
#pragma unroll 1
            for (int p = 0; p < 192; p += 8) {
#pragma unroll
                for (int q = 0; q < 8; q++)
                    acc8[q] += __half2float(baseh[(size_t)(p + q) * Dd]) * sbf[p + q];
            }
#pragma unroll
            for (int q = 0; q < 4; q++)
                acc8[q] += __half2float(baseh[(size_t)(192 + q) * Dd]) * sbf[192 + q];
            float s = ((acc8[0] + acc8[1]) + (acc8[2] + acc8[3])) +
                      ((acc8[4] + acc8[5]) + (acc8[6] + acc8[7]));
            g_x[b * 3072 + 512 + d] = s * gate;
        }
        gsync(++ph);

        // PD: full lstm gates via MMA: x[32,3072] @ W, 32 n-tiles x KS8
        if (bid < 256) {
            int nx = bid & 31, ky = bid >> 5;     // ky 0..7, k-chunk 384
            mma32_tile(g_x, 3072, ky * 384, 384,
                       lstm_w_ih, lstm_w_hh, 2560, 2048, 0, 0, 0,
                       nx * 64,
                       g_part + PART_B + (size_t)(ky * 32) * 2048, 2048,
                       As2, Bs2);
        }
        gsync(++ph);

        // PE: LSTM cell (64 units), KS=8
        if (bid < 64) {
            int idx = bid * 256 + tid;
            int b = idx >> 9, j = idx & 511;
            float s[4];
#pragma unroll
            for (int g = 0; g < 4; g++) s[g] = lstm_b[g * 512 + j];
#pragma unroll
            for (int ks = 0; ks < 8; ks++) {
                size_t base0 = PART_B + (size_t)(ks * 32 + b) * 2048 + j;
#pragma unroll
                for (int g = 0; g < 4; g++)
                    s[g] += g_part[base0 + g * 512];
            }
            float c_old = g_c[idx];
            float c_new = sigf(s[1]) * c_old + sigf(s[0]) * tanhf(s[2]);
            float h_new = sigf(s[3]) * tanhf(c_new);
            g_hall[((size_t)t * Bt + b) * Hh + j] = h_new;
            int active = (t < g_declen[b]);
            float h_keep = active ? h_new : g_h[idx];
            float c_keep = active ? c_new : c_old;
            g_h[idx] = h_keep;
            g_c[idx] = c_keep;
            g_x[b * 3072 + 2560 + j] = h_keep;
            if (t + 1 < Tt)
                g_x[b * 3072 + j] = g_embs[((size_t)b * Tt + (t + 1)) * Ee + j];
        }
        gsync(++ph);
    }

    // ---- FC: preds = h_all @ fc_w + b (785 tiles) ---------------------------
    for (int vb = bid; vb < 785; vb += GRD)
        fc_tile(vb % 5, vb / 5, fc_w, fc_b, out, As, Bs);
}

// ---------------- launch ----------------------------------------------------
extern "C" void kernel_launch(void* const* d_in, const int* in_sizes, int n_in,
                              void* d_out, int out_size) {
    const float* enc        = (const float*)d_in[0];
    const int*   caps_in    = (const int*)d_in[1];
    const int*   caplen     = (const int*)d_in[2];
    const float* enc_att_w  = (const float*)d_in[3];
    const float* enc_att_b  = (const float*)d_in[4];
    const float* dec_att_w  = (const float*)d_in[5];
    const float* dec_att_b  = (const float*)d_in[6];
    const float* full_att_w = (const float*)d_in[7];
    const float* full_att_b = (const float*)d_in[8];
    const float* emb        = (const float*)d_in[9];
    const float* init_h_w   = (const float*)d_in[10];
    const float* init_h_b   = (const float*)d_in[11];
    const float* init_c_w   = (const float*)d_in[12];
    const float* init_c_b   = (const float*)d_in[13];
    const float* f_beta_w   = (const float*)d_in[14];
    const float* f_beta_b   = (const float*)d_in[15];
    const float* lstm_w_ih  = (const float*)d_in[16];
    const float* lstm_w_hh  = (const float*)d_in[17];
    const float* lstm_b     = (const float*)d_in[18];
    const float* fc_w       = (const float*)d_in[19];
    const float* fc_b       = (const float*)d_in[20];
    float* out = (float*)d_out;

    prep_kernel<<<256, 256>>>(caplen, caps_in, emb, enc, out);
    mega_kernel<<<GRD, 256>>>(enc,
                              enc_att_w, enc_att_b,
                              init_h_w, init_h_b,
                              init_c_w, init_c_b,
                              dec_att_w, dec_att_b,
                              f_beta_w, f_beta_b,
                              full_att_w, full_att_b,
                              lstm_w_ih, lstm_w_hh, lstm_b,
                              fc_w, fc_b,
                              out);
}